// round 6
// baseline (speedup 1.0000x reference)
#include <cuda_runtime.h>
#include <cmath>

// Problem constants
#define B_    4096
#define IN_   1024
#define F_    512
#define HID_  128
#define D_    128
#define RH_   64
#define C_    10
#define R_    16
#define CH_   1280   // C_*HID_
#define BSEG_ 40
#define BCH_  32     // CH_/BSEG_

// k_weff linearized decomposition
#define NBLK_  592      // exactly 2 waves at 2 blocks/SM on 148 SMs
#define NSLOT_ 11       // max blocks covering one f-octet
#define UNITS_ 81920    // 64 octets * 1280 ch

// ---------------- device scratch ----------------
__device__ __align__(256) float g_rv[R_][D_];
__device__ __align__(256) float g_beff[R_];
__device__ __align__(256) float g_P[CH_][R_];             // P[ch][r] = w[r,c]*W2[r,h]
__device__ __align__(256) float g_WeffP[NSLOT_][R_][F_];  // k_weff slot partials
__device__ __align__(256) float g_WeffBP[BSEG_][R_][F_];  // fc1_b partials
__device__ __align__(256) float g_Weff[R_][F_];
__device__ __align__(256) float g_WxPart[8][IN_][R_];
__device__ __align__(256) float g_WxT[IN_][R_];           // [i][r]
__device__ __align__(256) float g_cst[R_];

// ---------------- packed f32x2 helpers ----------------
__device__ __forceinline__ unsigned long long pk2(float a, float b) {
    unsigned long long r;
    asm("mov.b64 %0, {%1,%2};" : "=l"(r) : "f"(a), "f"(b));
    return r;
}
__device__ __forceinline__ void upk2(unsigned long long v, float& a, float& b) {
    asm("mov.b64 {%0,%1}, %2;" : "=f"(a), "=f"(b) : "l"(v));
}
#define FMA2(acc, a, b) asm("fma.rn.f32x2 %0, %1, %2, %0;" : "+l"(acc) : "l"(a), "l"(b))

// ============ k_head: fused w, r1, rv, W2, b1, beff, P — block per r ============
__global__ void __launch_bounds__(256) k_head(
    const float* __restrict__ pref,
    const float* __restrict__ wm1_w, const float* __restrict__ wm1_b,
    const float* __restrict__ wm2_w, const float* __restrict__ wm2_b,
    const float* __restrict__ ray0_w, const float* __restrict__ ray0_b,
    const float* __restrict__ ray2_w, const float* __restrict__ ray2_b,
    const float* __restrict__ fc2_w, const float* __restrict__ fc2_b,
    const float* __restrict__ b1_w,  const float* __restrict__ b1_b,
    const float* __restrict__ b2_w,  const float* __restrict__ b2_b) {
    int r = blockIdx.x;
    int t = threadIdx.x;
    int warp = t >> 5, lane = t & 31;
    __shared__ float sh[16];
    __shared__ float sw[C_];
    __shared__ float sinv;
    __shared__ float sr1[RH_];
    __shared__ __align__(16) float srv[D_];
    __shared__ __align__(16) float sW2[HID_];
    __shared__ __align__(16) float sb1[HID_];
    __shared__ float sb0[HID_], sbb[HID_], sb2r[D_];

    // zero k_weff slot partials (16 blocks x 256 threads cover 90112 floats)
    for (int z = r * 256 + t; z < NSLOT_ * R_ * F_; z += 16 * 256)
        ((float*)g_WeffP)[z] = 0.f;

    float p0 = __ldg(pref + 2 * r), p1 = __ldg(pref + 2 * r + 1);
    if (t < 16) {
        float a = p0 * __ldg(wm1_w + t * 2) + p1 * __ldg(wm1_w + t * 2 + 1) + __ldg(wm1_b + t);
        sh[t] = a > 0.f ? a : 0.f;
    }
    __syncthreads();
    if (t < C_) {
        float a = __ldg(wm2_b + t);
        #pragma unroll
        for (int j = 0; j < 16; j++) a += sh[j] * __ldg(wm2_w + t * 16 + j);
        sw[t] = 1.f / (1.f + expf(-a));
    }
    __syncthreads();
    if (t == 0) {
        float s = 0.f;
        #pragma unroll
        for (int c = 0; c < C_; c++) s += sw[c];
        sinv = 1.f / s;
    }
    __syncthreads();
    if (t < C_) sw[t] *= sinv;
    __syncthreads();

    // r1 (t<64) and merged ray2 bias (t in [64,192))
    if (t < RH_) {
        float a = 0.f;
        #pragma unroll
        for (int c = 0; c < C_; c++) {
            float2 rw = __ldg((const float2*)(ray0_w + (c * RH_ + t) * 2));
            a += sw[c] * (p0 * rw.x + p1 * rw.y + __ldg(ray0_b + c * RH_ + t));
        }
        sr1[t] = a > 0.f ? a : 0.f;
    } else if (t < 64 + D_) {
        int d = t - 64;
        float b = 0.f;
        #pragma unroll
        for (int c = 0; c < C_; c++) b += sw[c] * __ldg(ray2_b + c * D_ + d);
        sb2r[d] = b;
    }
    __syncthreads();

    // rv: 8 warps x 16 oi, lanes over h
    {
        float r1a = sr1[lane], r1b = sr1[lane + 32];
        float acc[16];
        #pragma unroll
        for (int oi = 0; oi < 16; oi++) acc[oi] = 0.f;
        #pragma unroll
        for (int c = 0; c < C_; c++) {
            float wc = sw[c];
            #pragma unroll
            for (int oi = 0; oi < 16; oi++) {
                int o = warp * 16 + oi;
                const float* row = ray2_w + ((size_t)(c * D_ + o)) * RH_;
                acc[oi] += wc * (__ldg(row + lane) * r1a + __ldg(row + lane + 32) * r1b);
            }
        }
        #pragma unroll
        for (int oi = 0; oi < 16; oi++) {
            float s = acc[oi];
            #pragma unroll
            for (int off = 16; off > 0; off >>= 1) s += __shfl_down_sync(0xffffffffu, s, off);
            if (lane == 0) {
                int o = warp * 16 + oi;
                float v = s + sb2r[o];
                srv[o] = v;
                g_rv[r][o] = v;
            }
        }
    }
    // fc2/b1 biases (independent of rv)
    if (t < 128) {
        float b = 0.f;
        #pragma unroll
        for (int c = 0; c < C_; c++) b += sw[c] * __ldg(fc2_b + c * HID_ + t);
        sb0[t] = b;
    } else {
        int o = t - 128;
        float b = 0.f;
        #pragma unroll
        for (int c = 0; c < C_; c++) b += sw[c] * __ldg(b1_b + c * HID_ + o);
        sbb[o] = b;
    }
    __syncthreads();

    // W2 (warps 0-3) and b1 (warps 4-7): warp handles 32 o's
    {
        int kind = warp >> 2;
        int ob = (warp & 3) * 32;
        const float* Wc = kind ? b1_w : fc2_w;
        float4 rv4 = *(const float4*)&srv[lane * 4];
        float acc[32];
        #pragma unroll
        for (int oi = 0; oi < 32; oi++) acc[oi] = 0.f;
        #pragma unroll
        for (int c = 0; c < C_; c++) {
            float wc = sw[c];
            #pragma unroll
            for (int oi = 0; oi < 32; oi++) {
                int o = ob + oi;
                float4 v = __ldg((const float4*)(Wc + ((size_t)(c * HID_ + o)) * D_) + lane);
                acc[oi] += wc * (v.x * rv4.x + v.y * rv4.y + v.z * rv4.z + v.w * rv4.w);
            }
        }
        #pragma unroll
        for (int oi = 0; oi < 32; oi++) {
            float s = acc[oi];
            #pragma unroll
            for (int off = 16; off > 0; off >>= 1) s += __shfl_down_sync(0xffffffffu, s, off);
            if (lane == 0) {
                int o = ob + oi;
                if (kind) sb1[o] = s + sbb[o]; else sW2[o] = s + sb0[o];
            }
        }
    }
    __syncthreads();

    // beff (warp 0) + P fill (all threads)
    if (warp == 0) {
        float4 rv4 = *(const float4*)&srv[lane * 4];
        float acc = 0.f;
        #pragma unroll
        for (int c = 0; c < C_; c++) {
            float wc = sw[c];
            float4 bw = __ldg((const float4*)(b2_w + c * D_) + lane);
            acc += wc * (bw.x * rv4.x + bw.y * rv4.y + bw.z * rv4.z + bw.w * rv4.w);
            if (lane == 0) acc += wc * __ldg(b2_b + c);
        }
        float4 w24 = *(const float4*)&sW2[lane * 4];
        float4 b14 = *(const float4*)&sb1[lane * 4];
        acc += w24.x * b14.x + w24.y * b14.y + w24.z * b14.z + w24.w * b14.w;
        #pragma unroll
        for (int off = 16; off > 0; off >>= 1) acc += __shfl_down_sync(0xffffffffu, acc, off);
        if (lane == 0) g_beff[r] = acc;
    }
    for (int ch = t; ch < CH_; ch += 256)
        g_P[ch][r] = sw[ch >> 7] * sW2[ch & 127];
}

// ============ k_weff_bias: fc1_b partials, grid (4, BSEG_) ============
__global__ void __launch_bounds__(128) k_weff_bias(const float* __restrict__ fc1_b) {
    int f = blockIdx.x * 128 + threadIdx.x;
    int seg = blockIdx.y;
    float acc[16];
    #pragma unroll
    for (int r = 0; r < 16; r++) acc[r] = 0.f;
    int ch0 = seg * BCH_;
    #pragma unroll 8
    for (int i = 0; i < BCH_; i++) {
        int ch = ch0 + i;
        float v = __ldg(fc1_b + (size_t)ch * 512u + f);
        const float4* pp = (const float4*)g_P[ch];
        float4 pA = __ldg(pp + 0), pB = __ldg(pp + 1), pC = __ldg(pp + 2), pD = __ldg(pp + 3);
        acc[0] += pA.x * v;  acc[1] += pA.y * v;  acc[2] += pA.z * v;  acc[3] += pA.w * v;
        acc[4] += pB.x * v;  acc[5] += pB.y * v;  acc[6] += pB.z * v;  acc[7] += pB.w * v;
        acc[8] += pC.x * v;  acc[9] += pC.y * v;  acc[10] += pC.z * v; acc[11] += pC.w * v;
        acc[12] += pD.x * v; acc[13] += pD.y * v; acc[14] += pD.z * v; acc[15] += pD.w * v;
    }
    #pragma unroll
    for (int r = 0; r < 16; r++) g_WeffBP[seg][r][f] = acc[r];
}

// ============ k_weff: stream fc1_w (335 MB) -> Weff slot partials ============
// 592 blocks = 2 exact waves. Block i owns linear units [i*U/592,(i+1)*U/592)
// of (octet, ch) space; unit = 1 ch of one f-octet (8 f's, one per warp).
__global__ void __launch_bounds__(256, 2) k_weff(const float* __restrict__ fc1_w) {
    __shared__ __align__(16) float sP[144][16];   // 9 KB (ch-slice of P, zero-padded)
    __shared__ __align__(16) float srv[R_][D_];   // 8 KB
    int i = blockIdx.x;
    int t = threadIdx.x, warp = t >> 5, lane = t & 31;

    for (int z = t; z < R_ * D_; z += 256)
        ((float*)srv)[z] = ((const float*)g_rv)[z];

    long long a    = ((long long)i * UNITS_) / NBLK_;
    long long bend = ((long long)(i + 1) * UNITS_) / NBLK_;

    while (a < bend) {
        int oct = (int)(a / CH_);
        int c0  = (int)(a - (long long)oct * CH_);
        int len = (int)(((long long)(CH_ - c0) < (bend - a)) ? (long long)(CH_ - c0) : (bend - a));
        int lenp = (len + 3) & ~3;
        int f = oct * 8 + warp;

        __syncthreads();
        for (int z = t; z < lenp * 16; z += 256) {
            int j = z >> 4, rr = z & 15;
            ((float*)sP)[z] = (j < len) ? g_P[c0 + j][rr] : 0.f;
        }
        __syncthreads();

        const float4* base = (const float4*)fc1_w + (size_t)f * 32 + lane;
        unsigned long long acc[4][8];
        #pragma unroll
        for (int j = 0; j < 4; j++)
            #pragma unroll
            for (int rp = 0; rp < 8; rp++) acc[j][rp] = 0ull;

        float4 v[4], vn[4];
        #pragma unroll
        for (int q = 0; q < 4; q++) {
            int ch = c0 + q; if (ch > CH_ - 1) ch = CH_ - 1;
            v[q] = __ldg(base + (size_t)ch * 16384);
        }
        for (int cb = 0; cb < lenp; cb += 4) {
            if (cb + 4 < lenp) {
                #pragma unroll
                for (int q = 0; q < 4; q++) {
                    int ch = c0 + cb + 4 + q; if (ch > CH_ - 1) ch = CH_ - 1;
                    vn[q] = __ldg(base + (size_t)ch * 16384);
                }
            }
            #pragma unroll
            for (int q = 0; q < 4; q++) {
                const ulonglong2* pp = (const ulonglong2*)sP[cb + q];
                ulonglong2 pA = pp[0], pB = pp[1], pC = pp[2], pD = pp[3];
                unsigned long long u0 = pk2(v[q].x, v[q].x);
                unsigned long long u1 = pk2(v[q].y, v[q].y);
                unsigned long long u2 = pk2(v[q].z, v[q].z);
                unsigned long long u3 = pk2(v[q].w, v[q].w);
                FMA2(acc[0][0], u0, pA.x); FMA2(acc[0][1], u0, pA.y);
                FMA2(acc[0][2], u0, pB.x); FMA2(acc[0][3], u0, pB.y);
                FMA2(acc[0][4], u0, pC.x); FMA2(acc[0][5], u0, pC.y);
                FMA2(acc[0][6], u0, pD.x); FMA2(acc[0][7], u0, pD.y);
                FMA2(acc[1][0], u1, pA.x); FMA2(acc[1][1], u1, pA.y);
                FMA2(acc[1][2], u1, pB.x); FMA2(acc[1][3], u1, pB.y);
                FMA2(acc[1][4], u1, pC.x); FMA2(acc[1][5], u1, pC.y);
                FMA2(acc[1][6], u1, pD.x); FMA2(acc[1][7], u1, pD.y);
                FMA2(acc[2][0], u2, pA.x); FMA2(acc[2][1], u2, pA.y);
                FMA2(acc[2][2], u2, pB.x); FMA2(acc[2][3], u2, pB.y);
                FMA2(acc[2][4], u2, pC.x); FMA2(acc[2][5], u2, pC.y);
                FMA2(acc[2][6], u2, pD.x); FMA2(acc[2][7], u2, pD.y);
                FMA2(acc[3][0], u3, pA.x); FMA2(acc[3][1], u3, pA.y);
                FMA2(acc[3][2], u3, pB.x); FMA2(acc[3][3], u3, pB.y);
                FMA2(acc[3][4], u3, pC.x); FMA2(acc[3][5], u3, pC.y);
                FMA2(acc[3][6], u3, pD.x); FMA2(acc[3][7], u3, pD.y);
            }
            #pragma unroll
            for (int q = 0; q < 4; q++) v[q] = vn[q];
        }

        // epilogue: weight by rv[r][d], lane-reduce, write slot partial
        int d0 = lane * 4;
        float accr[16];
        #pragma unroll
        for (int r = 0; r < 16; r++) accr[r] = 0.f;
        #pragma unroll
        for (int j = 0; j < 4; j++) {
            #pragma unroll
            for (int rp = 0; rp < 8; rp++) {
                float a0, a1; upk2(acc[j][rp], a0, a1);
                accr[2 * rp]     += a0 * srv[2 * rp][d0 + j];
                accr[2 * rp + 1] += a1 * srv[2 * rp + 1][d0 + j];
            }
        }
        #pragma unroll
        for (int off = 16; off > 0; off >>= 1)
            #pragma unroll
            for (int r = 0; r < 16; r++)
                accr[r] += __shfl_down_sync(0xffffffffu, accr[r], off);
        if (lane == 0) {
            int slot = i - (oct * 37) / 4;   // first block of octet = floor(oct*592/64)
            #pragma unroll
            for (int r = 0; r < 16; r++) g_WeffP[slot][r][f] = accr[r];
        }
        a += len;
    }
}

// ============ k_wx: sum partials -> sW -> fold into base_w -> Wx partials ====
__global__ void __launch_bounds__(128) k_wx(const float* __restrict__ base_w) {
    __shared__ __align__(16) float sW[64][16];
    int i = blockIdx.x * 128 + threadIdx.x;
    int f0 = blockIdx.y * 64;
    for (int idx = threadIdx.x; idx < 64 * 16; idx += 128) {
        int ff = idx >> 4, r = idx & 15;
        float s = 0.f;
        #pragma unroll
        for (int sg = 0; sg < NSLOT_; sg++) s += g_WeffP[sg][r][f0 + ff];
        #pragma unroll
        for (int sg = 0; sg < BSEG_; sg++) s += g_WeffBP[sg][r][f0 + ff];
        sW[ff][r] = s;
        if (blockIdx.x == 0) g_Weff[r][f0 + ff] = s;
    }
    __syncthreads();
    unsigned long long acc[8];
    #pragma unroll
    for (int rp = 0; rp < 8; rp++) acc[rp] = 0ull;
    #pragma unroll 4
    for (int ff = 0; ff < 64; ff++) {
        float bw = __ldg(base_w + (size_t)(f0 + ff) * IN_ + i);
        unsigned long long b2 = pk2(bw, bw);
        const unsigned long long* pw = (const unsigned long long*)sW[ff];
        #pragma unroll
        for (int rp = 0; rp < 8; rp++) {
            unsigned long long tt = pw[rp];
            FMA2(acc[rp], b2, tt);
        }
    }
    float* o = &g_WxPart[blockIdx.y][i][0];
    #pragma unroll
    for (int rp = 0; rp < 8; rp++) {
        float a, b; upk2(acc[rp], a, b);
        o[2 * rp] = a; o[2 * rp + 1] = b;
    }
}

// ============ k_wx_reduce: sum partials + cst[r] ============
__global__ void k_wx_reduce(const float* __restrict__ base_b) {
    int idx = blockIdx.x * 256 + threadIdx.x;
    if (idx < IN_ * R_) {
        int i = idx >> 4, r = idx & 15;
        float s = 0.f;
        #pragma unroll
        for (int p = 0; p < 8; p++) s += g_WxPart[p][i][r];
        g_WxT[i][r] = s;
    }
    if (blockIdx.x == 0) {
        int warp = threadIdx.x >> 5, lane = threadIdx.x & 31;
        #pragma unroll
        for (int rr = warp; rr < R_; rr += 8) {
            float a = 0.f;
            #pragma unroll
            for (int kk = 0; kk < 16; kk++) {
                int ff = kk * 32 + lane;
                a += g_Weff[rr][ff] * __ldg(base_b + ff);
            }
            #pragma unroll
            for (int off = 16; off > 0; off >>= 1) a += __shfl_down_sync(0xffffffffu, a, off);
            if (lane == 0) g_cst[rr] = g_beff[rr] + a;
        }
    }
}

// ============ k_out: out[r,b] = x[b]·Wx[r] + cst[r]; 2 b per warp ============
__global__ void __launch_bounds__(256) k_out(const float* __restrict__ x,
                                             float* __restrict__ out, int write_raw) {
    int warp = threadIdx.x >> 5, lane = threadIdx.x & 31;
    int b0 = (blockIdx.x * 8 + warp) * 2;
    unsigned long long acc[2][8];
    #pragma unroll
    for (int j = 0; j < 2; j++)
        #pragma unroll
        for (int rp = 0; rp < 8; rp++) acc[j][rp] = 0ull;

    #pragma unroll
    for (int k = 0; k < 8; k++) {
        float4 xv0 = __ldg((const float4*)(x + (size_t)(b0 + 0) * IN_) + k * 32 + lane);
        float4 xv1 = __ldg((const float4*)(x + (size_t)(b0 + 1) * IN_) + k * 32 + lane);
        int ib = (k * 32 + lane) * 4;
        #pragma unroll
        for (int di = 0; di < 4; di++) {
            const ulonglong2* wr = (const ulonglong2*)g_WxT[ib + di];
            ulonglong2 wA = __ldg(wr + 0), wB = __ldg(wr + 1);
            ulonglong2 wC = __ldg(wr + 2), wD = __ldg(wr + 3);
            float x0c = di == 0 ? xv0.x : di == 1 ? xv0.y : di == 2 ? xv0.z : xv0.w;
            float x1c = di == 0 ? xv1.x : di == 1 ? xv1.y : di == 2 ? xv1.z : xv1.w;
            unsigned long long u0 = pk2(x0c, x0c), u1 = pk2(x1c, x1c);
            FMA2(acc[0][0], u0, wA.x); FMA2(acc[0][1], u0, wA.y);
            FMA2(acc[0][2], u0, wB.x); FMA2(acc[0][3], u0, wB.y);
            FMA2(acc[0][4], u0, wC.x); FMA2(acc[0][5], u0, wC.y);
            FMA2(acc[0][6], u0, wD.x); FMA2(acc[0][7], u0, wD.y);
            FMA2(acc[1][0], u1, wA.x); FMA2(acc[1][1], u1, wA.y);
            FMA2(acc[1][2], u1, wB.x); FMA2(acc[1][3], u1, wB.y);
            FMA2(acc[1][4], u1, wC.x); FMA2(acc[1][5], u1, wC.y);
            FMA2(acc[1][6], u1, wD.x); FMA2(acc[1][7], u1, wD.y);
        }
    }
    float accr[2][16];
    #pragma unroll
    for (int j = 0; j < 2; j++)
        #pragma unroll
        for (int rp = 0; rp < 8; rp++) upk2(acc[j][rp], accr[j][2 * rp], accr[j][2 * rp + 1]);
    #pragma unroll
    for (int off = 16; off > 0; off >>= 1)
        #pragma unroll
        for (int j = 0; j < 2; j++)
            #pragma unroll
            for (int r = 0; r < 16; r++)
                accr[j][r] += __shfl_down_sync(0xffffffffu, accr[j][r], off);
    if (lane == 0) {
        #pragma unroll
        for (int j = 0; j < 2; j++) {
            #pragma unroll
            for (int r = 0; r < 16; r++) {
                float v = accr[j][r] + g_cst[r];
                out[r * B_ + b0 + j] = 1.f / (1.f + expf(-v));
                if (write_raw) out[R_ * B_ + r * B_ + b0 + j] = v;
            }
        }
    }
}

// ---------------- launcher ----------------
extern "C" void kernel_launch(void* const* d_in, const int* in_sizes, int n_in,
                              void* d_out, int out_size) {
    const float* x      = (const float*)d_in[0];
    const float* pref   = (const float*)d_in[1];
    const float* base_w = (const float*)d_in[2];
    const float* base_b = (const float*)d_in[3];
    const float* wm1_w  = (const float*)d_in[4];
    const float* wm1_b  = (const float*)d_in[5];
    const float* wm2_w  = (const float*)d_in[6];
    const float* wm2_b  = (const float*)d_in[7];
    const float* ray0_w = (const float*)d_in[8];
    const float* ray0_b = (const float*)d_in[9];
    const float* ray2_w = (const float*)d_in[10];
    const float* ray2_b = (const float*)d_in[11];
    const float* fc1_w  = (const float*)d_in[12];
    const float* fc1_b  = (const float*)d_in[13];
    const float* b1_w   = (const float*)d_in[14];
    const float* b1_b   = (const float*)d_in[15];
    const float* fc2_w  = (const float*)d_in[16];
    const float* fc2_b  = (const float*)d_in[17];
    const float* b2_w   = (const float*)d_in[18];
    const float* b2_b   = (const float*)d_in[19];
    float* out = (float*)d_out;
    int write_raw = (out_size >= 2 * R_ * B_) ? 1 : 0;

    k_head<<<R_, 256>>>(pref, wm1_w, wm1_b, wm2_w, wm2_b,
                        ray0_w, ray0_b, ray2_w, ray2_b,
                        fc2_w, fc2_b, b1_w, b1_b, b2_w, b2_b);
    k_weff_bias<<<dim3(4, BSEG_), 128>>>(fc1_b);
    k_weff<<<NBLK_, 256>>>(fc1_w);
    k_wx<<<dim3(8, 8), 128>>>(base_w);
    k_wx_reduce<<<64, 256>>>(base_b);
    k_out<<<B_ / 16, 256>>>(x, out, write_raw);
}

// round 7
// speedup vs baseline: 1.1144x; 1.1144x over previous
#include <cuda_runtime.h>
#include <cmath>

// Problem constants
#define B_    4096
#define IN_   1024
#define F_    512
#define HID_  128
#define D_    128
#define RH_   64
#define C_    10
#define R_    16
#define CH_   1280   // C_*HID_
#define NSEG_ 8
#define CHSEG_ 160   // CH_/NSEG_
#define BSEG_ 20
#define BCH_  64     // CH_/BSEG_
#define NPLANE_ (NSEG_ + BSEG_)

// ---------------- device scratch ----------------
__device__ __align__(256) float g_rv[R_][D_];
__device__ __align__(256) float g_beff[R_];
__device__ __align__(256) float g_P[CH_][R_];            // P[ch][r] = w[r,c]*W2[r,h]
__device__ __align__(256) float g_WeffP[NSEG_][R_][F_];  // k_weff partials
__device__ __align__(256) float g_WeffBP[BSEG_][R_][F_]; // fc1_b partials
__device__ __align__(256) float g_Weff[R_][F_];
__device__ __align__(256) float g_WxPart[16][IN_][R_];
__device__ __align__(256) float g_WxT[IN_][R_];          // [i][r]
__device__ __align__(256) float g_cst[R_];

// ---------------- packed f32x2 helpers ----------------
__device__ __forceinline__ unsigned long long pk2(float a, float b) {
    unsigned long long r;
    asm("mov.b64 %0, {%1,%2};" : "=l"(r) : "f"(a), "f"(b));
    return r;
}
__device__ __forceinline__ void upk2(unsigned long long v, float& a, float& b) {
    asm("mov.b64 {%0,%1}, %2;" : "=f"(a), "=f"(b) : "l"(v));
}
#define FMA2(acc, a, b) asm("fma.rn.f32x2 %0, %1, %2, %0;" : "+l"(acc) : "l"(a), "l"(b))

// ============ k_head: fused w, r1, rv, W2, b1, beff, P — block per r ============
__global__ void __launch_bounds__(256) k_head(
    const float* __restrict__ pref,
    const float* __restrict__ wm1_w, const float* __restrict__ wm1_b,
    const float* __restrict__ wm2_w, const float* __restrict__ wm2_b,
    const float* __restrict__ ray0_w, const float* __restrict__ ray0_b,
    const float* __restrict__ ray2_w, const float* __restrict__ ray2_b,
    const float* __restrict__ fc2_w, const float* __restrict__ fc2_b,
    const float* __restrict__ b1_w,  const float* __restrict__ b1_b,
    const float* __restrict__ b2_w,  const float* __restrict__ b2_b) {
    int r = blockIdx.x;
    int t = threadIdx.x;
    int warp = t >> 5, lane = t & 31;
    __shared__ float sh[16];
    __shared__ float sw[C_];
    __shared__ float sinv;
    __shared__ float sr1[RH_];
    __shared__ __align__(16) float srv[D_];
    __shared__ __align__(16) float sW2[HID_];
    __shared__ __align__(16) float sb1[HID_];
    __shared__ float sb0[HID_], sbb[HID_], sb2r[D_];

    float p0 = __ldg(pref + 2 * r), p1 = __ldg(pref + 2 * r + 1);
    if (t < 16) {
        float a = p0 * __ldg(wm1_w + t * 2) + p1 * __ldg(wm1_w + t * 2 + 1) + __ldg(wm1_b + t);
        sh[t] = a > 0.f ? a : 0.f;
    }
    __syncthreads();
    if (t < C_) {
        float a = __ldg(wm2_b + t);
        #pragma unroll
        for (int j = 0; j < 16; j++) a += sh[j] * __ldg(wm2_w + t * 16 + j);
        sw[t] = 1.f / (1.f + expf(-a));
    }
    __syncthreads();
    if (t == 0) {
        float s = 0.f;
        #pragma unroll
        for (int c = 0; c < C_; c++) s += sw[c];
        sinv = 1.f / s;
    }
    __syncthreads();
    if (t < C_) sw[t] *= sinv;
    __syncthreads();

    if (t < RH_) {
        float a = 0.f;
        #pragma unroll
        for (int c = 0; c < C_; c++) {
            float2 rw = __ldg((const float2*)(ray0_w + (c * RH_ + t) * 2));
            a += sw[c] * (p0 * rw.x + p1 * rw.y + __ldg(ray0_b + c * RH_ + t));
        }
        sr1[t] = a > 0.f ? a : 0.f;
    } else if (t < 64 + D_) {
        int d = t - 64;
        float b = 0.f;
        #pragma unroll
        for (int c = 0; c < C_; c++) b += sw[c] * __ldg(ray2_b + c * D_ + d);
        sb2r[d] = b;
    }
    __syncthreads();

    // rv: 8 warps x 16 oi, lanes over h
    {
        float r1a = sr1[lane], r1b = sr1[lane + 32];
        float acc[16];
        #pragma unroll
        for (int oi = 0; oi < 16; oi++) acc[oi] = 0.f;
        #pragma unroll
        for (int c = 0; c < C_; c++) {
            float wc = sw[c];
            #pragma unroll
            for (int oi = 0; oi < 16; oi++) {
                int o = warp * 16 + oi;
                const float* row = ray2_w + ((size_t)(c * D_ + o)) * RH_;
                acc[oi] += wc * (__ldg(row + lane) * r1a + __ldg(row + lane + 32) * r1b);
            }
        }
        #pragma unroll
        for (int oi = 0; oi < 16; oi++) {
            float s = acc[oi];
            #pragma unroll
            for (int off = 16; off > 0; off >>= 1) s += __shfl_down_sync(0xffffffffu, s, off);
            if (lane == 0) {
                int o = warp * 16 + oi;
                float v = s + sb2r[o];
                srv[o] = v;
                g_rv[r][o] = v;
            }
        }
    }
    if (t < 128) {
        float b = 0.f;
        #pragma unroll
        for (int c = 0; c < C_; c++) b += sw[c] * __ldg(fc2_b + c * HID_ + t);
        sb0[t] = b;
    } else {
        int o = t - 128;
        float b = 0.f;
        #pragma unroll
        for (int c = 0; c < C_; c++) b += sw[c] * __ldg(b1_b + c * HID_ + o);
        sbb[o] = b;
    }
    __syncthreads();

    // W2 (warps 0-3) and b1 (warps 4-7): warp handles 32 o's
    {
        int kind = warp >> 2;
        int ob = (warp & 3) * 32;
        const float* Wc = kind ? b1_w : fc2_w;
        float4 rv4 = *(const float4*)&srv[lane * 4];
        float acc[32];
        #pragma unroll
        for (int oi = 0; oi < 32; oi++) acc[oi] = 0.f;
        #pragma unroll
        for (int c = 0; c < C_; c++) {
            float wc = sw[c];
            #pragma unroll
            for (int oi = 0; oi < 32; oi++) {
                int o = ob + oi;
                float4 v = __ldg((const float4*)(Wc + ((size_t)(c * HID_ + o)) * D_) + lane);
                acc[oi] += wc * (v.x * rv4.x + v.y * rv4.y + v.z * rv4.z + v.w * rv4.w);
            }
        }
        #pragma unroll
        for (int oi = 0; oi < 32; oi++) {
            float s = acc[oi];
            #pragma unroll
            for (int off = 16; off > 0; off >>= 1) s += __shfl_down_sync(0xffffffffu, s, off);
            if (lane == 0) {
                int o = ob + oi;
                if (kind) sb1[o] = s + sbb[o]; else sW2[o] = s + sb0[o];
            }
        }
    }
    __syncthreads();

    if (warp == 0) {
        float4 rv4 = *(const float4*)&srv[lane * 4];
        float acc = 0.f;
        #pragma unroll
        for (int c = 0; c < C_; c++) {
            float wc = sw[c];
            float4 bw = __ldg((const float4*)(b2_w + c * D_) + lane);
            acc += wc * (bw.x * rv4.x + bw.y * rv4.y + bw.z * rv4.z + bw.w * rv4.w);
            if (lane == 0) acc += wc * __ldg(b2_b + c);
        }
        float4 w24 = *(const float4*)&sW2[lane * 4];
        float4 b14 = *(const float4*)&sb1[lane * 4];
        acc += w24.x * b14.x + w24.y * b14.y + w24.z * b14.z + w24.w * b14.w;
        #pragma unroll
        for (int off = 16; off > 0; off >>= 1) acc += __shfl_down_sync(0xffffffffu, acc, off);
        if (lane == 0) g_beff[r] = acc;
    }
    for (int ch = t; ch < CH_; ch += 256)
        g_P[ch][r] = sw[ch >> 7] * sW2[ch & 127];
}

// ============ k_weff_bias: fc1_b partials, grid (4, BSEG_) ============
__global__ void __launch_bounds__(128) k_weff_bias(const float* __restrict__ fc1_b) {
    int f = blockIdx.x * 128 + threadIdx.x;
    int seg = blockIdx.y;
    float acc[16];
    #pragma unroll
    for (int r = 0; r < 16; r++) acc[r] = 0.f;
    int ch0 = seg * BCH_;
    #pragma unroll 8
    for (int i = 0; i < BCH_; i++) {
        int ch = ch0 + i;
        float v = __ldg(fc1_b + (size_t)ch * 512u + f);
        const float4* pp = (const float4*)g_P[ch];
        float4 pA = __ldg(pp + 0), pB = __ldg(pp + 1), pC = __ldg(pp + 2), pD = __ldg(pp + 3);
        acc[0] += pA.x * v;  acc[1] += pA.y * v;  acc[2] += pA.z * v;  acc[3] += pA.w * v;
        acc[4] += pB.x * v;  acc[5] += pB.y * v;  acc[6] += pB.z * v;  acc[7] += pB.w * v;
        acc[8] += pC.x * v;  acc[9] += pC.y * v;  acc[10] += pC.z * v; acc[11] += pC.w * v;
        acc[12] += pD.x * v; acc[13] += pD.y * v; acc[14] += pD.z * v; acc[15] += pD.w * v;
    }
    #pragma unroll
    for (int r = 0; r < 16; r++) g_WeffBP[seg][r][f] = acc[r];
}

// ============ k_weff: stream fc1_w (335 MB) -> Weff partials (R5 version) ====
// grid (64 f-groups, NSEG_ ch-segs); 256 thr = 8 warps. Warp owns ONE f and the
// whole 160-ch segment; lane owns 4 d's (float4 loads, 4-ch prefetch).
__global__ void __launch_bounds__(256, 2) k_weff(const float* __restrict__ fc1_w) {
    __shared__ __align__(16) float sP[CHSEG_][16];   // 10 KB
    int seg = blockIdx.y;
    int t = threadIdx.x;
    int warp = t >> 5, lane = t & 31;
    int f = blockIdx.x * 8 + warp;

    for (int idx = t; idx < CHSEG_ * 16; idx += 256)
        ((float*)sP)[idx] = ((const float*)g_P[seg * CHSEG_])[idx];
    __syncthreads();

    const float4* base = (const float4*)(fc1_w
        + (size_t)(seg * CHSEG_) * 65536u + (size_t)f * 128u) + lane;

    unsigned long long acc[4][8];
    #pragma unroll
    for (int j = 0; j < 4; j++)
        #pragma unroll
        for (int rp = 0; rp < 8; rp++) acc[j][rp] = 0ull;

    float4 v[4], vn[4];
    #pragma unroll
    for (int q = 0; q < 4; q++) v[q] = __ldg(base + q * 16384);

    for (int cb = 0; cb < CHSEG_; cb += 4) {
        if (cb + 4 < CHSEG_) {
            #pragma unroll
            for (int q = 0; q < 4; q++)
                vn[q] = __ldg(base + (cb + 4 + q) * 16384);
        }
        #pragma unroll
        for (int q = 0; q < 4; q++) {
            int ch = cb + q;
            const ulonglong2* pp = (const ulonglong2*)sP[ch];
            ulonglong2 pA = pp[0], pB = pp[1], pC = pp[2], pD = pp[3];
            unsigned long long u0 = pk2(v[q].x, v[q].x);
            unsigned long long u1 = pk2(v[q].y, v[q].y);
            unsigned long long u2 = pk2(v[q].z, v[q].z);
            unsigned long long u3 = pk2(v[q].w, v[q].w);
            FMA2(acc[0][0], u0, pA.x); FMA2(acc[0][1], u0, pA.y);
            FMA2(acc[0][2], u0, pB.x); FMA2(acc[0][3], u0, pB.y);
            FMA2(acc[0][4], u0, pC.x); FMA2(acc[0][5], u0, pC.y);
            FMA2(acc[0][6], u0, pD.x); FMA2(acc[0][7], u0, pD.y);
            FMA2(acc[1][0], u1, pA.x); FMA2(acc[1][1], u1, pA.y);
            FMA2(acc[1][2], u1, pB.x); FMA2(acc[1][3], u1, pB.y);
            FMA2(acc[1][4], u1, pC.x); FMA2(acc[1][5], u1, pC.y);
            FMA2(acc[1][6], u1, pD.x); FMA2(acc[1][7], u1, pD.y);
            FMA2(acc[2][0], u2, pA.x); FMA2(acc[2][1], u2, pA.y);
            FMA2(acc[2][2], u2, pB.x); FMA2(acc[2][3], u2, pB.y);
            FMA2(acc[2][4], u2, pC.x); FMA2(acc[2][5], u2, pC.y);
            FMA2(acc[2][6], u2, pD.x); FMA2(acc[2][7], u2, pD.y);
            FMA2(acc[3][0], u3, pA.x); FMA2(acc[3][1], u3, pA.y);
            FMA2(acc[3][2], u3, pB.x); FMA2(acc[3][3], u3, pB.y);
            FMA2(acc[3][4], u3, pC.x); FMA2(acc[3][5], u3, pC.y);
            FMA2(acc[3][6], u3, pD.x); FMA2(acc[3][7], u3, pD.y);
        }
        #pragma unroll
        for (int q = 0; q < 4; q++) v[q] = vn[q];
    }

    int d0 = lane * 4;
    float accr[16];
    #pragma unroll
    for (int r = 0; r < 16; r++) accr[r] = 0.f;
    #pragma unroll
    for (int j = 0; j < 4; j++) {
        #pragma unroll
        for (int rp = 0; rp < 8; rp++) {
            float a0, a1; upk2(acc[j][rp], a0, a1);
            accr[2 * rp]     += a0 * g_rv[2 * rp][d0 + j];
            accr[2 * rp + 1] += a1 * g_rv[2 * rp + 1][d0 + j];
        }
    }
    #pragma unroll
    for (int off = 16; off > 0; off >>= 1)
        #pragma unroll
        for (int r = 0; r < 16; r++)
            accr[r] += __shfl_down_sync(0xffffffffu, accr[r], off);
    if (lane == 0) {
        #pragma unroll
        for (int r = 0; r < 16; r++) g_WeffP[seg][r][f] = accr[r];
    }
}

// ============ k_wx: sum 28 planes -> sW -> fold base_w -> Wx partials ============
// grid (8 i-blocks, 16 f-chunks of 32), 128 threads
__global__ void __launch_bounds__(128) k_wx(const float* __restrict__ base_w) {
    __shared__ __align__(16) float sW[32][16];
    int i = blockIdx.x * 128 + threadIdx.x;
    int f0 = blockIdx.y * 32;
    for (int idx = threadIdx.x; idx < 32 * 16; idx += 128) {
        int ff = idx >> 4, r = idx & 15;
        float s = 0.f;
        #pragma unroll
        for (int sg = 0; sg < NSEG_; sg++) s += g_WeffP[sg][r][f0 + ff];
        #pragma unroll
        for (int sg = 0; sg < BSEG_; sg++) s += g_WeffBP[sg][r][f0 + ff];
        sW[ff][r] = s;
        if (blockIdx.x == 0) g_Weff[r][f0 + ff] = s;
    }
    __syncthreads();
    unsigned long long acc[8];
    #pragma unroll
    for (int rp = 0; rp < 8; rp++) acc[rp] = 0ull;
    #pragma unroll 4
    for (int ff = 0; ff < 32; ff++) {
        float bw = __ldg(base_w + (size_t)(f0 + ff) * IN_ + i);
        unsigned long long b2 = pk2(bw, bw);
        const unsigned long long* pw = (const unsigned long long*)sW[ff];
        #pragma unroll
        for (int rp = 0; rp < 8; rp++) {
            unsigned long long tt = pw[rp];
            FMA2(acc[rp], b2, tt);
        }
    }
    float* o = &g_WxPart[blockIdx.y][i][0];
    #pragma unroll
    for (int rp = 0; rp < 8; rp++) {
        float a, b; upk2(acc[rp], a, b);
        o[2 * rp] = a; o[2 * rp + 1] = b;
    }
}

// ============ k_wx_reduce: sum 16 partial planes + cst[r] ============
__global__ void k_wx_reduce(const float* __restrict__ base_b) {
    int idx = blockIdx.x * 256 + threadIdx.x;
    if (idx < IN_ * R_) {
        int i = idx >> 4, r = idx & 15;
        float s = 0.f;
        #pragma unroll
        for (int p = 0; p < 16; p++) s += g_WxPart[p][i][r];
        g_WxT[i][r] = s;
    }
    if (blockIdx.x == 0) {
        int warp = threadIdx.x >> 5, lane = threadIdx.x & 31;
        #pragma unroll
        for (int rr = warp; rr < R_; rr += 8) {
            float a = 0.f;
            #pragma unroll
            for (int kk = 0; kk < 16; kk++) {
                int ff = kk * 32 + lane;
                a += g_Weff[rr][ff] * __ldg(base_b + ff);
            }
            #pragma unroll
            for (int off = 16; off > 0; off >>= 1) a += __shfl_down_sync(0xffffffffu, a, off);
            if (lane == 0) g_cst[rr] = g_beff[rr] + a;
        }
    }
}

// ============ k_out: out[r,b] = x[b]·Wx[r] + cst[r]; 2 b per warp ============
__global__ void __launch_bounds__(256) k_out(const float* __restrict__ x,
                                             float* __restrict__ out, int write_raw) {
    int warp = threadIdx.x >> 5, lane = threadIdx.x & 31;
    int b0 = (blockIdx.x * 8 + warp) * 2;
    unsigned long long acc[2][8];
    #pragma unroll
    for (int j = 0; j < 2; j++)
        #pragma unroll
        for (int rp = 0; rp < 8; rp++) acc[j][rp] = 0ull;

    #pragma unroll
    for (int k = 0; k < 8; k++) {
        float4 xv0 = __ldg((const float4*)(x + (size_t)(b0 + 0) * IN_) + k * 32 + lane);
        float4 xv1 = __ldg((const float4*)(x + (size_t)(b0 + 1) * IN_) + k * 32 + lane);
        int ib = (k * 32 + lane) * 4;
        #pragma unroll
        for (int di = 0; di < 4; di++) {
            const ulonglong2* wr = (const ulonglong2*)g_WxT[ib + di];
            ulonglong2 wA = __ldg(wr + 0), wB = __ldg(wr + 1);
            ulonglong2 wC = __ldg(wr + 2), wD = __ldg(wr + 3);
            float x0c = di == 0 ? xv0.x : di == 1 ? xv0.y : di == 2 ? xv0.z : xv0.w;
            float x1c = di == 0 ? xv1.x : di == 1 ? xv1.y : di == 2 ? xv1.z : xv1.w;
            unsigned long long u0 = pk2(x0c, x0c), u1 = pk2(x1c, x1c);
            FMA2(acc[0][0], u0, wA.x); FMA2(acc[0][1], u0, wA.y);
            FMA2(acc[0][2], u0, wB.x); FMA2(acc[0][3], u0, wB.y);
            FMA2(acc[0][4], u0, wC.x); FMA2(acc[0][5], u0, wC.y);
            FMA2(acc[0][6], u0, wD.x); FMA2(acc[0][7], u0, wD.y);
            FMA2(acc[1][0], u1, wA.x); FMA2(acc[1][1], u1, wA.y);
            FMA2(acc[1][2], u1, wB.x); FMA2(acc[1][3], u1, wB.y);
            FMA2(acc[1][4], u1, wC.x); FMA2(acc[1][5], u1, wC.y);
            FMA2(acc[1][6], u1, wD.x); FMA2(acc[1][7], u1, wD.y);
        }
    }
    float accr[2][16];
    #pragma unroll
    for (int j = 0; j < 2; j++)
        #pragma unroll
        for (int rp = 0; rp < 8; rp++) upk2(acc[j][rp], accr[j][2 * rp], accr[j][2 * rp + 1]);
    #pragma unroll
    for (int off = 16; off > 0; off >>= 1)
        #pragma unroll
        for (int j = 0; j < 2; j++)
            #pragma unroll
            for (int r = 0; r < 16; r++)
                accr[j][r] += __shfl_down_sync(0xffffffffu, accr[j][r], off);
    if (lane == 0) {
        #pragma unroll
        for (int j = 0; j < 2; j++) {
            #pragma unroll
            for (int r = 0; r < 16; r++) {
                float v = accr[j][r] + g_cst[r];
                out[r * B_ + b0 + j] = 1.f / (1.f + expf(-v));
                if (write_raw) out[R_ * B_ + r * B_ + b0 + j] = v;
            }
        }
    }
}

// ---------------- launcher ----------------
extern "C" void kernel_launch(void* const* d_in, const int* in_sizes, int n_in,
                              void* d_out, int out_size) {
    const float* x      = (const float*)d_in[0];
    const float* pref   = (const float*)d_in[1];
    const float* base_w = (const float*)d_in[2];
    const float* base_b = (const float*)d_in[3];
    const float* wm1_w  = (const float*)d_in[4];
    const float* wm1_b  = (const float*)d_in[5];
    const float* wm2_w  = (const float*)d_in[6];
    const float* wm2_b  = (const float*)d_in[7];
    const float* ray0_w = (const float*)d_in[8];
    const float* ray0_b = (const float*)d_in[9];
    const float* ray2_w = (const float*)d_in[10];
    const float* ray2_b = (const float*)d_in[11];
    const float* fc1_w  = (const float*)d_in[12];
    const float* fc1_b  = (const float*)d_in[13];
    const float* b1_w   = (const float*)d_in[14];
    const float* b1_b   = (const float*)d_in[15];
    const float* fc2_w  = (const float*)d_in[16];
    const float* fc2_b  = (const float*)d_in[17];
    const float* b2_w   = (const float*)d_in[18];
    const float* b2_b   = (const float*)d_in[19];
    float* out = (float*)d_out;
    int write_raw = (out_size >= 2 * R_ * B_) ? 1 : 0;

    k_head<<<R_, 256>>>(pref, wm1_w, wm1_b, wm2_w, wm2_b,
                        ray0_w, ray0_b, ray2_w, ray2_b,
                        fc2_w, fc2_b, b1_w, b1_b, b2_w, b2_b);
    k_weff_bias<<<dim3(4, BSEG_), 128>>>(fc1_b);
    k_weff<<<dim3(F_ / 8, NSEG_), 256>>>(fc1_w);
    k_wx<<<dim3(8, 16), 128>>>(base_w);          // launch #4 -> profiled
    k_wx_reduce<<<64, 256>>>(base_b);
    k_out<<<B_ / 16, 256>>>(x, out, write_raw);
}

// round 8
// speedup vs baseline: 1.2979x; 1.1647x over previous
#include <cuda_runtime.h>
#include <cmath>

// Problem constants
#define B_    4096
#define IN_   1024
#define F_    512
#define HID_  128
#define D_    128
#define RH_   64
#define C_    10
#define R_    16
#define CH_   1280   // C_*HID_
#define NSEG_ 8
#define CHSEG_ 160   // CH_/NSEG_

// ---------------- device scratch ----------------
__device__ __align__(256) float g_rv[R_][D_];
__device__ __align__(256) float g_P[CH_][R_];            // P[ch][r] = w[r,c]*W2[r,h]
__device__ __align__(256) float g_WeffP[NSEG_][R_][F_];  // k_weff partials (incl. bias)
__device__ __align__(256) float g_WxT[IN_][R_];          // [i][r], atomic-accumulated
__device__ __align__(256) float g_cst[R_];               // beff + Weff·base_b (atomics)

// ---------------- packed f32x2 helpers ----------------
__device__ __forceinline__ unsigned long long pk2(float a, float b) {
    unsigned long long r;
    asm("mov.b64 %0, {%1,%2};" : "=l"(r) : "f"(a), "f"(b));
    return r;
}
__device__ __forceinline__ void upk2(unsigned long long v, float& a, float& b) {
    asm("mov.b64 {%0,%1}, %2;" : "=f"(a), "=f"(b) : "l"(v));
}
#define FMA2(acc, a, b) asm("fma.rn.f32x2 %0, %1, %2, %0;" : "+l"(acc) : "l"(a), "l"(b))

// ============ k_head: fused w, r1, rv, W2, b1, beff->cst, P; zero WxT ============
__global__ void __launch_bounds__(256) k_head(
    const float* __restrict__ pref,
    const float* __restrict__ wm1_w, const float* __restrict__ wm1_b,
    const float* __restrict__ wm2_w, const float* __restrict__ wm2_b,
    const float* __restrict__ ray0_w, const float* __restrict__ ray0_b,
    const float* __restrict__ ray2_w, const float* __restrict__ ray2_b,
    const float* __restrict__ fc2_w, const float* __restrict__ fc2_b,
    const float* __restrict__ b1_w,  const float* __restrict__ b1_b,
    const float* __restrict__ b2_w,  const float* __restrict__ b2_b) {
    int r = blockIdx.x;
    int t = threadIdx.x;
    int warp = t >> 5, lane = t & 31;
    __shared__ float sh[16];
    __shared__ float sw[C_];
    __shared__ float sinv;
    __shared__ float sr1[RH_];
    __shared__ __align__(16) float srv[D_];
    __shared__ __align__(16) float sW2[HID_];
    __shared__ __align__(16) float sb1[HID_];
    __shared__ float sb0[HID_], sbb[HID_], sb2r[D_];

    // zero g_WxT for this call (graph replay safe): 16 blocks x 256 cover 16384
    for (int z = r * 256 + t; z < IN_ * R_; z += 16 * 256)
        ((float*)g_WxT)[z] = 0.f;

    float p0 = __ldg(pref + 2 * r), p1 = __ldg(pref + 2 * r + 1);
    if (t < 16) {
        float a = p0 * __ldg(wm1_w + t * 2) + p1 * __ldg(wm1_w + t * 2 + 1) + __ldg(wm1_b + t);
        sh[t] = a > 0.f ? a : 0.f;
    }
    __syncthreads();
    if (t < C_) {
        float a = __ldg(wm2_b + t);
        #pragma unroll
        for (int j = 0; j < 16; j++) a += sh[j] * __ldg(wm2_w + t * 16 + j);
        sw[t] = 1.f / (1.f + expf(-a));
    }
    __syncthreads();
    if (t == 0) {
        float s = 0.f;
        #pragma unroll
        for (int c = 0; c < C_; c++) s += sw[c];
        sinv = 1.f / s;
    }
    __syncthreads();
    if (t < C_) sw[t] *= sinv;
    __syncthreads();

    if (t < RH_) {
        float a = 0.f;
        #pragma unroll
        for (int c = 0; c < C_; c++) {
            float2 rw = __ldg((const float2*)(ray0_w + (c * RH_ + t) * 2));
            a += sw[c] * (p0 * rw.x + p1 * rw.y + __ldg(ray0_b + c * RH_ + t));
        }
        sr1[t] = a > 0.f ? a : 0.f;
    } else if (t < 64 + D_) {
        int d = t - 64;
        float b = 0.f;
        #pragma unroll
        for (int c = 0; c < C_; c++) b += sw[c] * __ldg(ray2_b + c * D_ + d);
        sb2r[d] = b;
    }
    __syncthreads();

    // rv: 8 warps x 16 oi, lanes over h
    {
        float r1a = sr1[lane], r1b = sr1[lane + 32];
        float acc[16];
        #pragma unroll
        for (int oi = 0; oi < 16; oi++) acc[oi] = 0.f;
        #pragma unroll
        for (int c = 0; c < C_; c++) {
            float wc = sw[c];
            #pragma unroll
            for (int oi = 0; oi < 16; oi++) {
                int o = warp * 16 + oi;
                const float* row = ray2_w + ((size_t)(c * D_ + o)) * RH_;
                acc[oi] += wc * (__ldg(row + lane) * r1a + __ldg(row + lane + 32) * r1b);
            }
        }
        #pragma unroll
        for (int oi = 0; oi < 16; oi++) {
            float s = acc[oi];
            #pragma unroll
            for (int off = 16; off > 0; off >>= 1) s += __shfl_down_sync(0xffffffffu, s, off);
            if (lane == 0) {
                int o = warp * 16 + oi;
                float v = s + sb2r[o];
                srv[o] = v;
                g_rv[r][o] = v;
            }
        }
    }
    if (t < 128) {
        float b = 0.f;
        #pragma unroll
        for (int c = 0; c < C_; c++) b += sw[c] * __ldg(fc2_b + c * HID_ + t);
        sb0[t] = b;
    } else {
        int o = t - 128;
        float b = 0.f;
        #pragma unroll
        for (int c = 0; c < C_; c++) b += sw[c] * __ldg(b1_b + c * HID_ + o);
        sbb[o] = b;
    }
    __syncthreads();

    // W2 (warps 0-3) and b1 (warps 4-7): warp handles 32 o's
    {
        int kind = warp >> 2;
        int ob = (warp & 3) * 32;
        const float* Wc = kind ? b1_w : fc2_w;
        float4 rv4 = *(const float4*)&srv[lane * 4];
        float acc[32];
        #pragma unroll
        for (int oi = 0; oi < 32; oi++) acc[oi] = 0.f;
        #pragma unroll
        for (int c = 0; c < C_; c++) {
            float wc = sw[c];
            #pragma unroll
            for (int oi = 0; oi < 32; oi++) {
                int o = ob + oi;
                float4 v = __ldg((const float4*)(Wc + ((size_t)(c * HID_ + o)) * D_) + lane);
                acc[oi] += wc * (v.x * rv4.x + v.y * rv4.y + v.z * rv4.z + v.w * rv4.w);
            }
        }
        #pragma unroll
        for (int oi = 0; oi < 32; oi++) {
            float s = acc[oi];
            #pragma unroll
            for (int off = 16; off > 0; off >>= 1) s += __shfl_down_sync(0xffffffffu, s, off);
            if (lane == 0) {
                int o = ob + oi;
                if (kind) sb1[o] = s + sbb[o]; else sW2[o] = s + sb0[o];
            }
        }
    }
    __syncthreads();

    if (warp == 0) {
        float4 rv4 = *(const float4*)&srv[lane * 4];
        float acc = 0.f;
        #pragma unroll
        for (int c = 0; c < C_; c++) {
            float wc = sw[c];
            float4 bw = __ldg((const float4*)(b2_w + c * D_) + lane);
            acc += wc * (bw.x * rv4.x + bw.y * rv4.y + bw.z * rv4.z + bw.w * rv4.w);
            if (lane == 0) acc += wc * __ldg(b2_b + c);
        }
        float4 w24 = *(const float4*)&sW2[lane * 4];
        float4 b14 = *(const float4*)&sb1[lane * 4];
        acc += w24.x * b14.x + w24.y * b14.y + w24.z * b14.z + w24.w * b14.w;
        #pragma unroll
        for (int off = 16; off > 0; off >>= 1) acc += __shfl_down_sync(0xffffffffu, acc, off);
        if (lane == 0) g_cst[r] = acc;   // beff; k_wx atomically adds Weff·base_b
    }
    for (int ch = t; ch < CH_; ch += 256)
        g_P[ch][r] = sw[ch >> 7] * sW2[ch & 127];
}

// ============ k_weff: stream fc1_w -> Weff partials; fc1_b bias fused ============
// grid (64 f-groups, NSEG_ ch-segs); 8 warps, warp owns ONE f; lane owns 4 d.
__global__ void __launch_bounds__(256, 2) k_weff(const float* __restrict__ fc1_w,
                                                 const float* __restrict__ fc1_b) {
    __shared__ __align__(16) float sP[CHSEG_][16];   // 10 KB
    int seg = blockIdx.y;
    int t = threadIdx.x;
    int warp = t >> 5, lane = t & 31;
    int f = blockIdx.x * 8 + warp;

    for (int idx = t; idx < CHSEG_ * 16; idx += 256)
        ((float*)sP)[idx] = ((const float*)g_P[seg * CHSEG_])[idx];
    __syncthreads();

    const float4* base = (const float4*)(fc1_w
        + (size_t)(seg * CHSEG_) * 65536u + (size_t)f * 128u) + lane;

    unsigned long long acc[4][8];
    #pragma unroll
    for (int j = 0; j < 4; j++)
        #pragma unroll
        for (int rp = 0; rp < 8; rp++) acc[j][rp] = 0ull;

    float4 v[4], vn[4];
    #pragma unroll
    for (int q = 0; q < 4; q++) v[q] = __ldg(base + q * 16384);

    for (int cb = 0; cb < CHSEG_; cb += 4) {
        if (cb + 4 < CHSEG_) {
            #pragma unroll
            for (int q = 0; q < 4; q++)
                vn[q] = __ldg(base + (cb + 4 + q) * 16384);
        }
        #pragma unroll
        for (int q = 0; q < 4; q++) {
            int ch = cb + q;
            const ulonglong2* pp = (const ulonglong2*)sP[ch];
            ulonglong2 pA = pp[0], pB = pp[1], pC = pp[2], pD = pp[3];
            unsigned long long u0 = pk2(v[q].x, v[q].x);
            unsigned long long u1 = pk2(v[q].y, v[q].y);
            unsigned long long u2 = pk2(v[q].z, v[q].z);
            unsigned long long u3 = pk2(v[q].w, v[q].w);
            FMA2(acc[0][0], u0, pA.x); FMA2(acc[0][1], u0, pA.y);
            FMA2(acc[0][2], u0, pB.x); FMA2(acc[0][3], u0, pB.y);
            FMA2(acc[0][4], u0, pC.x); FMA2(acc[0][5], u0, pC.y);
            FMA2(acc[0][6], u0, pD.x); FMA2(acc[0][7], u0, pD.y);
            FMA2(acc[1][0], u1, pA.x); FMA2(acc[1][1], u1, pA.y);
            FMA2(acc[1][2], u1, pB.x); FMA2(acc[1][3], u1, pB.y);
            FMA2(acc[1][4], u1, pC.x); FMA2(acc[1][5], u1, pC.y);
            FMA2(acc[1][6], u1, pD.x); FMA2(acc[1][7], u1, pD.y);
            FMA2(acc[2][0], u2, pA.x); FMA2(acc[2][1], u2, pA.y);
            FMA2(acc[2][2], u2, pB.x); FMA2(acc[2][3], u2, pB.y);
            FMA2(acc[2][4], u2, pC.x); FMA2(acc[2][5], u2, pC.y);
            FMA2(acc[2][6], u2, pD.x); FMA2(acc[2][7], u2, pD.y);
            FMA2(acc[3][0], u3, pA.x); FMA2(acc[3][1], u3, pA.y);
            FMA2(acc[3][2], u3, pB.x); FMA2(acc[3][3], u3, pB.y);
            FMA2(acc[3][4], u3, pC.x); FMA2(acc[3][5], u3, pC.y);
            FMA2(acc[3][6], u3, pD.x); FMA2(acc[3][7], u3, pD.y);
        }
        #pragma unroll
        for (int q = 0; q < 4; q++) v[q] = vn[q];
    }

    // fused fc1_b bias: lane covers ch = lane, lane+32, ... (5 iters)
    unsigned long long bacc[8];
    #pragma unroll
    for (int rp = 0; rp < 8; rp++) bacc[rp] = 0ull;
    #pragma unroll
    for (int it = 0; it < CHSEG_ / 32; it++) {
        int chl = it * 32 + lane;
        float bv = __ldg(fc1_b + (size_t)(seg * CHSEG_ + chl) * 512u + f);
        unsigned long long vv = pk2(bv, bv);
        const ulonglong2* pp = (const ulonglong2*)sP[chl];
        ulonglong2 pA = pp[0], pB = pp[1], pC = pp[2], pD = pp[3];
        FMA2(bacc[0], vv, pA.x); FMA2(bacc[1], vv, pA.y);
        FMA2(bacc[2], vv, pB.x); FMA2(bacc[3], vv, pB.y);
        FMA2(bacc[4], vv, pC.x); FMA2(bacc[5], vv, pC.y);
        FMA2(bacc[6], vv, pD.x); FMA2(bacc[7], vv, pD.y);
    }

    // epilogue: weight main acc by rv[r][d], add bias, reduce over lanes
    int d0 = lane * 4;
    float accr[16];
    #pragma unroll
    for (int rp = 0; rp < 8; rp++) {
        float a0, a1; upk2(bacc[rp], a0, a1);
        accr[2 * rp] = a0; accr[2 * rp + 1] = a1;
    }
    #pragma unroll
    for (int j = 0; j < 4; j++) {
        #pragma unroll
        for (int rp = 0; rp < 8; rp++) {
            float a0, a1; upk2(acc[j][rp], a0, a1);
            accr[2 * rp]     += a0 * g_rv[2 * rp][d0 + j];
            accr[2 * rp + 1] += a1 * g_rv[2 * rp + 1][d0 + j];
        }
    }
    #pragma unroll
    for (int off = 16; off > 0; off >>= 1)
        #pragma unroll
        for (int r = 0; r < 16; r++)
            accr[r] += __shfl_down_sync(0xffffffffu, accr[r], off);
    if (lane == 0) {
        #pragma unroll
        for (int r = 0; r < 16; r++) g_WeffP[seg][r][f] = accr[r];
    }
}

// ============ k_wx: sum 8 planes -> fold base_w -> atomic Wx; cst inline ======
__global__ void __launch_bounds__(128) k_wx(const float* __restrict__ base_w,
                                            const float* __restrict__ base_b) {
    __shared__ __align__(16) float sW[32][16];
    int t = threadIdx.x;
    int f0 = blockIdx.y * 32;
    for (int idx = t; idx < 32 * 16; idx += 128) {
        int ff = idx >> 4, r = idx & 15;
        float s = 0.f;
        #pragma unroll
        for (int sg = 0; sg < NSEG_; sg++) s += g_WeffP[sg][r][f0 + ff];
        sW[ff][r] = s;
    }
    __syncthreads();
    if (blockIdx.x == 0) {
        int r = t >> 3, fq = (t & 7) * 4;
        float p = 0.f;
        #pragma unroll
        for (int j = 0; j < 4; j++) p += sW[fq + j][r] * __ldg(base_b + f0 + fq + j);
        atomicAdd(&g_cst[r], p);
    }
    int i = blockIdx.x * 128 + t;
    unsigned long long acc[8];
    #pragma unroll
    for (int rp = 0; rp < 8; rp++) acc[rp] = 0ull;
    #pragma unroll 4
    for (int ff = 0; ff < 32; ff++) {
        float bw = __ldg(base_w + (size_t)(f0 + ff) * IN_ + i);
        unsigned long long b2 = pk2(bw, bw);
        const unsigned long long* pw = (const unsigned long long*)sW[ff];
        #pragma unroll
        for (int rp = 0; rp < 8; rp++) {
            unsigned long long tt = pw[rp];
            FMA2(acc[rp], b2, tt);
        }
    }
    #pragma unroll
    for (int rp = 0; rp < 8; rp++) {
        float a, b; upk2(acc[rp], a, b);
        atomicAdd(&g_WxT[i][2 * rp], a);
        atomicAdd(&g_WxT[i][2 * rp + 1], b);
    }
}

// ============ k_out: out[r,b] = x[b]·Wx[r] + cst[r]; 4 b per warp ============
__global__ void __launch_bounds__(256) k_out(const float* __restrict__ x,
                                             float* __restrict__ out, int write_raw) {
    int warp = threadIdx.x >> 5, lane = threadIdx.x & 31;
    int b0 = (blockIdx.x * 8 + warp) * 4;
    unsigned long long acc[4][8];
    #pragma unroll
    for (int j = 0; j < 4; j++)
        #pragma unroll
        for (int rp = 0; rp < 8; rp++) acc[j][rp] = 0ull;

    #pragma unroll
    for (int k = 0; k < 8; k++) {
        float4 xv0 = __ldg((const float4*)(x + (size_t)(b0 + 0) * IN_) + k * 32 + lane);
        float4 xv1 = __ldg((const float4*)(x + (size_t)(b0 + 1) * IN_) + k * 32 + lane);
        float4 xv2 = __ldg((const float4*)(x + (size_t)(b0 + 2) * IN_) + k * 32 + lane);
        float4 xv3 = __ldg((const float4*)(x + (size_t)(b0 + 3) * IN_) + k * 32 + lane);
        int ib = (k * 32 + lane) * 4;
        #pragma unroll
        for (int di = 0; di < 4; di++) {
            const ulonglong2* wr = (const ulonglong2*)g_WxT[ib + di];
            ulonglong2 wA = __ldg(wr + 0), wB = __ldg(wr + 1);
            ulonglong2 wC = __ldg(wr + 2), wD = __ldg(wr + 3);
            float c0 = di == 0 ? xv0.x : di == 1 ? xv0.y : di == 2 ? xv0.z : xv0.w;
            float c1 = di == 0 ? xv1.x : di == 1 ? xv1.y : di == 2 ? xv1.z : xv1.w;
            float c2 = di == 0 ? xv2.x : di == 1 ? xv2.y : di == 2 ? xv2.z : xv2.w;
            float c3 = di == 0 ? xv3.x : di == 1 ? xv3.y : di == 2 ? xv3.z : xv3.w;
            unsigned long long u0 = pk2(c0, c0), u1 = pk2(c1, c1);
            unsigned long long u2 = pk2(c2, c2), u3 = pk2(c3, c3);
            FMA2(acc[0][0], u0, wA.x); FMA2(acc[0][1], u0, wA.y);
            FMA2(acc[0][2], u0, wB.x); FMA2(acc[0][3], u0, wB.y);
            FMA2(acc[0][4], u0, wC.x); FMA2(acc[0][5], u0, wC.y);
            FMA2(acc[0][6], u0, wD.x); FMA2(acc[0][7], u0, wD.y);
            FMA2(acc[1][0], u1, wA.x); FMA2(acc[1][1], u1, wA.y);
            FMA2(acc[1][2], u1, wB.x); FMA2(acc[1][3], u1, wB.y);
            FMA2(acc[1][4], u1, wC.x); FMA2(acc[1][5], u1, wC.y);
            FMA2(acc[1][6], u1, wD.x); FMA2(acc[1][7], u1, wD.y);
            FMA2(acc[2][0], u2, wA.x); FMA2(acc[2][1], u2, wA.y);
            FMA2(acc[2][2], u2, wB.x); FMA2(acc[2][3], u2, wB.y);
            FMA2(acc[2][4], u2, wC.x); FMA2(acc[2][5], u2, wC.y);
            FMA2(acc[2][6], u2, wD.x); FMA2(acc[2][7], u2, wD.y);
            FMA2(acc[3][0], u3, wA.x); FMA2(acc[3][1], u3, wA.y);
            FMA2(acc[3][2], u3, wB.x); FMA2(acc[3][3], u3, wB.y);
            FMA2(acc[3][4], u3, wC.x); FMA2(acc[3][5], u3, wC.y);
            FMA2(acc[3][6], u3, wD.x); FMA2(acc[3][7], u3, wD.y);
        }
    }
    float accr[4][16];
    #pragma unroll
    for (int j = 0; j < 4; j++)
        #pragma unroll
        for (int rp = 0; rp < 8; rp++) upk2(acc[j][rp], accr[j][2 * rp], accr[j][2 * rp + 1]);
    #pragma unroll
    for (int off = 16; off > 0; off >>= 1)
        #pragma unroll
        for (int j = 0; j < 4; j++)
            #pragma unroll
            for (int r = 0; r < 16; r++)
                accr[j][r] += __shfl_down_sync(0xffffffffu, accr[j][r], off);
    if (lane == 0) {
        #pragma unroll
        for (int j = 0; j < 4; j++) {
            #pragma unroll
            for (int r = 0; r < 16; r++) {
                float v = accr[j][r] + g_cst[r];
                out[r * B_ + b0 + j] = 1.f / (1.f + expf(-v));
                if (write_raw) out[R_ * B_ + r * B_ + b0 + j] = v;
            }
        }
    }
}

// ---------------- launcher ----------------
extern "C" void kernel_launch(void* const* d_in, const int* in_sizes, int n_in,
                              void* d_out, int out_size) {
    const float* x      = (const float*)d_in[0];
    const float* pref   = (const float*)d_in[1];
    const float* base_w = (const float*)d_in[2];
    const float* base_b = (const float*)d_in[3];
    const float* wm1_w  = (const float*)d_in[4];
    const float* wm1_b  = (const float*)d_in[5];
    const float* wm2_w  = (const float*)d_in[6];
    const float* wm2_b  = (const float*)d_in[7];
    const float* ray0_w = (const float*)d_in[8];
    const float* ray0_b = (const float*)d_in[9];
    const float* ray2_w = (const float*)d_in[10];
    const float* ray2_b = (const float*)d_in[11];
    const float* fc1_w  = (const float*)d_in[12];
    const float* fc1_b  = (const float*)d_in[13];
    const float* b1_w   = (const float*)d_in[14];
    const float* b1_b   = (const float*)d_in[15];
    const float* fc2_w  = (const float*)d_in[16];
    const float* fc2_b  = (const float*)d_in[17];
    const float* b2_w   = (const float*)d_in[18];
    const float* b2_b   = (const float*)d_in[19];
    float* out = (float*)d_out;
    int write_raw = (out_size >= 2 * R_ * B_) ? 1 : 0;

    k_head<<<R_, 256>>>(pref, wm1_w, wm1_b, wm2_w, wm2_b,
                        ray0_w, ray0_b, ray2_w, ray2_b,
                        fc2_w, fc2_b, b1_w, b1_b, b2_w, b2_b);
    k_weff<<<dim3(F_ / 8, NSEG_), 256>>>(fc1_w, fc1_b);
    k_wx<<<dim3(8, 16), 128>>>(base_w, base_b);
    k_out<<<B_ / 32, 256>>>(x, out, write_raw);   // launch #4 -> profiled
}

// round 9
// speedup vs baseline: 1.3929x; 1.0732x over previous
#include <cuda_runtime.h>
#include <cmath>

// Problem constants
#define B_    4096
#define IN_   1024
#define F_    512
#define HID_  128
#define D_    128
#define RH_   64
#define C_    10
#define R_    16
#define CH_   1280   // C_*HID_
#define NSEG_ 8
#define CHSEG_ 160   // CH_/NSEG_

// ---------------- device scratch ----------------
__device__ __align__(256) float g_rv[R_][D_];
__device__ __align__(256) float g_P[CH_][R_];            // P[ch][r] = w[r,c]*W2[r,h]
__device__ __align__(256) float g_WeffP[NSEG_][R_][F_];  // k_weff partials (incl. bias)
__device__ __align__(256) float g_WxT[IN_][R_];          // [i][r], atomic-accumulated
__device__ __align__(256) float g_cst[R_];               // beff + Weff·base_b (atomics)

// ---------------- packed f32x2 helpers ----------------
__device__ __forceinline__ unsigned long long pk2(float a, float b) {
    unsigned long long r;
    asm("mov.b64 %0, {%1,%2};" : "=l"(r) : "f"(a), "f"(b));
    return r;
}
__device__ __forceinline__ void upk2(unsigned long long v, float& a, float& b) {
    asm("mov.b64 {%0,%1}, %2;" : "=f"(a), "=f"(b) : "l"(v));
}
#define FMA2(acc, a, b) asm("fma.rn.f32x2 %0, %1, %2, %0;" : "+l"(acc) : "l"(a), "l"(b))

// ============ k_head: fused w, r1, rv, W2, b1, beff->cst, P; zero WxT ============
__global__ void __launch_bounds__(256) k_head(
    const float* __restrict__ pref,
    const float* __restrict__ wm1_w, const float* __restrict__ wm1_b,
    const float* __restrict__ wm2_w, const float* __restrict__ wm2_b,
    const float* __restrict__ ray0_w, const float* __restrict__ ray0_b,
    const float* __restrict__ ray2_w, const float* __restrict__ ray2_b,
    const float* __restrict__ fc2_w, const float* __restrict__ fc2_b,
    const float* __restrict__ b1_w,  const float* __restrict__ b1_b,
    const float* __restrict__ b2_w,  const float* __restrict__ b2_b) {
    int r = blockIdx.x;
    int t = threadIdx.x;
    int warp = t >> 5, lane = t & 31;
    __shared__ float sh[16];
    __shared__ float sw[C_];
    __shared__ float sinv;
    __shared__ float sr1[RH_];
    __shared__ __align__(16) float srv[D_];
    __shared__ __align__(16) float sW2[HID_];
    __shared__ __align__(16) float sb1[HID_];
    __shared__ float sb0[HID_], sbb[HID_], sb2r[D_];

    // zero g_WxT for this call (graph replay safe)
    for (int z = r * 256 + t; z < IN_ * R_; z += 16 * 256)
        ((float*)g_WxT)[z] = 0.f;

    float p0 = __ldg(pref + 2 * r), p1 = __ldg(pref + 2 * r + 1);
    if (t < 16) {
        float a = p0 * __ldg(wm1_w + t * 2) + p1 * __ldg(wm1_w + t * 2 + 1) + __ldg(wm1_b + t);
        sh[t] = a > 0.f ? a : 0.f;
    }
    __syncthreads();
    if (t < C_) {
        float a = __ldg(wm2_b + t);
        #pragma unroll
        for (int j = 0; j < 16; j++) a += sh[j] * __ldg(wm2_w + t * 16 + j);
        sw[t] = 1.f / (1.f + expf(-a));
    }
    __syncthreads();
    if (t == 0) {
        float s = 0.f;
        #pragma unroll
        for (int c = 0; c < C_; c++) s += sw[c];
        sinv = 1.f / s;
    }
    __syncthreads();
    if (t < C_) sw[t] *= sinv;
    __syncthreads();

    if (t < RH_) {
        float a = 0.f;
        #pragma unroll
        for (int c = 0; c < C_; c++) {
            float2 rw = __ldg((const float2*)(ray0_w + (c * RH_ + t) * 2));
            a += sw[c] * (p0 * rw.x + p1 * rw.y + __ldg(ray0_b + c * RH_ + t));
        }
        sr1[t] = a > 0.f ? a : 0.f;
    } else if (t < 64 + D_) {
        int d = t - 64;
        float b = 0.f;
        #pragma unroll
        for (int c = 0; c < C_; c++) b += sw[c] * __ldg(ray2_b + c * D_ + d);
        sb2r[d] = b;
    }
    __syncthreads();

    // rv: 8 warps x 16 oi, lanes over h
    {
        float r1a = sr1[lane], r1b = sr1[lane + 32];
        float acc[16];
        #pragma unroll
        for (int oi = 0; oi < 16; oi++) acc[oi] = 0.f;
        #pragma unroll
        for (int c = 0; c < C_; c++) {
            float wc = sw[c];
            #pragma unroll
            for (int oi = 0; oi < 16; oi++) {
                int o = warp * 16 + oi;
                const float* row = ray2_w + ((size_t)(c * D_ + o)) * RH_;
                acc[oi] += wc * (__ldg(row + lane) * r1a + __ldg(row + lane + 32) * r1b);
            }
        }
        #pragma unroll
        for (int oi = 0; oi < 16; oi++) {
            float s = acc[oi];
            #pragma unroll
            for (int off = 16; off > 0; off >>= 1) s += __shfl_down_sync(0xffffffffu, s, off);
            if (lane == 0) {
                int o = warp * 16 + oi;
                float v = s + sb2r[o];
                srv[o] = v;
                g_rv[r][o] = v;
            }
        }
    }
    if (t < 128) {
        float b = 0.f;
        #pragma unroll
        for (int c = 0; c < C_; c++) b += sw[c] * __ldg(fc2_b + c * HID_ + t);
        sb0[t] = b;
    } else {
        int o = t - 128;
        float b = 0.f;
        #pragma unroll
        for (int c = 0; c < C_; c++) b += sw[c] * __ldg(b1_b + c * HID_ + o);
        sbb[o] = b;
    }
    __syncthreads();

    // W2 (warps 0-3) and b1 (warps 4-7): warp handles 32 o's
    {
        int kind = warp >> 2;
        int ob = (warp & 3) * 32;
        const float* Wc = kind ? b1_w : fc2_w;
        float4 rv4 = *(const float4*)&srv[lane * 4];
        float acc[32];
        #pragma unroll
        for (int oi = 0; oi < 32; oi++) acc[oi] = 0.f;
        #pragma unroll
        for (int c = 0; c < C_; c++) {
            float wc = sw[c];
            #pragma unroll
            for (int oi = 0; oi < 32; oi++) {
                int o = ob + oi;
                float4 v = __ldg((const float4*)(Wc + ((size_t)(c * HID_ + o)) * D_) + lane);
                acc[oi] += wc * (v.x * rv4.x + v.y * rv4.y + v.z * rv4.z + v.w * rv4.w);
            }
        }
        #pragma unroll
        for (int oi = 0; oi < 32; oi++) {
            float s = acc[oi];
            #pragma unroll
            for (int off = 16; off > 0; off >>= 1) s += __shfl_down_sync(0xffffffffu, s, off);
            if (lane == 0) {
                int o = ob + oi;
                if (kind) sb1[o] = s + sbb[o]; else sW2[o] = s + sb0[o];
            }
        }
    }
    __syncthreads();

    if (warp == 0) {
        float4 rv4 = *(const float4*)&srv[lane * 4];
        float acc = 0.f;
        #pragma unroll
        for (int c = 0; c < C_; c++) {
            float wc = sw[c];
            float4 bw = __ldg((const float4*)(b2_w + c * D_) + lane);
            acc += wc * (bw.x * rv4.x + bw.y * rv4.y + bw.z * rv4.z + bw.w * rv4.w);
            if (lane == 0) acc += wc * __ldg(b2_b + c);
        }
        float4 w24 = *(const float4*)&sW2[lane * 4];
        float4 b14 = *(const float4*)&sb1[lane * 4];
        acc += w24.x * b14.x + w24.y * b14.y + w24.z * b14.z + w24.w * b14.w;
        #pragma unroll
        for (int off = 16; off > 0; off >>= 1) acc += __shfl_down_sync(0xffffffffu, acc, off);
        if (lane == 0) g_cst[r] = acc;   // beff; k_wx atomically adds Weff·base_b
    }
    for (int ch = t; ch < CH_; ch += 256)
        g_P[ch][r] = sw[ch >> 7] * sW2[ch & 127];
}

// ============ k_weff: stream fc1_w -> Weff partials; fc1_b bias fused ============
__global__ void __launch_bounds__(256, 2) k_weff(const float* __restrict__ fc1_w,
                                                 const float* __restrict__ fc1_b) {
    __shared__ __align__(16) float sP[CHSEG_][16];   // 10 KB
    int seg = blockIdx.y;
    int t = threadIdx.x;
    int warp = t >> 5, lane = t & 31;
    int f = blockIdx.x * 8 + warp;

    for (int idx = t; idx < CHSEG_ * 16; idx += 256)
        ((float*)sP)[idx] = ((const float*)g_P[seg * CHSEG_])[idx];
    __syncthreads();

    const float4* base = (const float4*)(fc1_w
        + (size_t)(seg * CHSEG_) * 65536u + (size_t)f * 128u) + lane;

    unsigned long long acc[4][8];
    #pragma unroll
    for (int j = 0; j < 4; j++)
        #pragma unroll
        for (int rp = 0; rp < 8; rp++) acc[j][rp] = 0ull;

    float4 v[4], vn[4];
    #pragma unroll
    for (int q = 0; q < 4; q++) v[q] = __ldg(base + q * 16384);

    for (int cb = 0; cb < CHSEG_; cb += 4) {
        if (cb + 4 < CHSEG_) {
            #pragma unroll
            for (int q = 0; q < 4; q++)
                vn[q] = __ldg(base + (cb + 4 + q) * 16384);
        }
        #pragma unroll
        for (int q = 0; q < 4; q++) {
            int ch = cb + q;
            const ulonglong2* pp = (const ulonglong2*)sP[ch];
            ulonglong2 pA = pp[0], pB = pp[1], pC = pp[2], pD = pp[3];
            unsigned long long u0 = pk2(v[q].x, v[q].x);
            unsigned long long u1 = pk2(v[q].y, v[q].y);
            unsigned long long u2 = pk2(v[q].z, v[q].z);
            unsigned long long u3 = pk2(v[q].w, v[q].w);
            FMA2(acc[0][0], u0, pA.x); FMA2(acc[0][1], u0, pA.y);
            FMA2(acc[0][2], u0, pB.x); FMA2(acc[0][3], u0, pB.y);
            FMA2(acc[0][4], u0, pC.x); FMA2(acc[0][5], u0, pC.y);
            FMA2(acc[0][6], u0, pD.x); FMA2(acc[0][7], u0, pD.y);
            FMA2(acc[1][0], u1, pA.x); FMA2(acc[1][1], u1, pA.y);
            FMA2(acc[1][2], u1, pB.x); FMA2(acc[1][3], u1, pB.y);
            FMA2(acc[1][4], u1, pC.x); FMA2(acc[1][5], u1, pC.y);
            FMA2(acc[1][6], u1, pD.x); FMA2(acc[1][7], u1, pD.y);
            FMA2(acc[2][0], u2, pA.x); FMA2(acc[2][1], u2, pA.y);
            FMA2(acc[2][2], u2, pB.x); FMA2(acc[2][3], u2, pB.y);
            FMA2(acc[2][4], u2, pC.x); FMA2(acc[2][5], u2, pC.y);
            FMA2(acc[2][6], u2, pD.x); FMA2(acc[2][7], u2, pD.y);
            FMA2(acc[3][0], u3, pA.x); FMA2(acc[3][1], u3, pA.y);
            FMA2(acc[3][2], u3, pB.x); FMA2(acc[3][3], u3, pB.y);
            FMA2(acc[3][4], u3, pC.x); FMA2(acc[3][5], u3, pC.y);
            FMA2(acc[3][6], u3, pD.x); FMA2(acc[3][7], u3, pD.y);
        }
        #pragma unroll
        for (int q = 0; q < 4; q++) v[q] = vn[q];
    }

    // fused fc1_b bias: lane covers ch = lane, lane+32, ... (5 iters)
    unsigned long long bacc[8];
    #pragma unroll
    for (int rp = 0; rp < 8; rp++) bacc[rp] = 0ull;
    #pragma unroll
    for (int it = 0; it < CHSEG_ / 32; it++) {
        int chl = it * 32 + lane;
        float bv = __ldg(fc1_b + (size_t)(seg * CHSEG_ + chl) * 512u + f);
        unsigned long long vv = pk2(bv, bv);
        const ulonglong2* pp = (const ulonglong2*)sP[chl];
        ulonglong2 pA = pp[0], pB = pp[1], pC = pp[2], pD = pp[3];
        FMA2(bacc[0], vv, pA.x); FMA2(bacc[1], vv, pA.y);
        FMA2(bacc[2], vv, pB.x); FMA2(bacc[3], vv, pB.y);
        FMA2(bacc[4], vv, pC.x); FMA2(bacc[5], vv, pC.y);
        FMA2(bacc[6], vv, pD.x); FMA2(bacc[7], vv, pD.y);
    }

    int d0 = lane * 4;
    float accr[16];
    #pragma unroll
    for (int rp = 0; rp < 8; rp++) {
        float a0, a1; upk2(bacc[rp], a0, a1);
        accr[2 * rp] = a0; accr[2 * rp + 1] = a1;
    }
    #pragma unroll
    for (int j = 0; j < 4; j++) {
        #pragma unroll
        for (int rp = 0; rp < 8; rp++) {
            float a0, a1; upk2(acc[j][rp], a0, a1);
            accr[2 * rp]     += a0 * g_rv[2 * rp][d0 + j];
            accr[2 * rp + 1] += a1 * g_rv[2 * rp + 1][d0 + j];
        }
    }
    #pragma unroll
    for (int off = 16; off > 0; off >>= 1)
        #pragma unroll
        for (int r = 0; r < 16; r++)
            accr[r] += __shfl_down_sync(0xffffffffu, accr[r], off);
    if (lane == 0) {
        #pragma unroll
        for (int r = 0; r < 16; r++) g_WeffP[seg][r][f] = accr[r];
    }
}

// ============ k_wx: sum 8 planes -> fold base_w -> atomic Wx; cst inline ======
__global__ void __launch_bounds__(128) k_wx(const float* __restrict__ base_w,
                                            const float* __restrict__ base_b) {
    __shared__ __align__(16) float sW[32][16];
    int t = threadIdx.x;
    int f0 = blockIdx.y * 32;
    for (int idx = t; idx < 32 * 16; idx += 128) {
        int ff = idx >> 4, r = idx & 15;
        float s = 0.f;
        #pragma unroll
        for (int sg = 0; sg < NSEG_; sg++) s += g_WeffP[sg][r][f0 + ff];
        sW[ff][r] = s;
    }
    __syncthreads();
    if (blockIdx.x == 0) {
        int r = t >> 3, fq = (t & 7) * 4;
        float p = 0.f;
        #pragma unroll
        for (int j = 0; j < 4; j++) p += sW[fq + j][r] * __ldg(base_b + f0 + fq + j);
        atomicAdd(&g_cst[r], p);
    }
    int i = blockIdx.x * 128 + t;
    unsigned long long acc[8];
    #pragma unroll
    for (int rp = 0; rp < 8; rp++) acc[rp] = 0ull;
    #pragma unroll 4
    for (int ff = 0; ff < 32; ff++) {
        float bw = __ldg(base_w + (size_t)(f0 + ff) * IN_ + i);
        unsigned long long b2 = pk2(bw, bw);
        const unsigned long long* pw = (const unsigned long long*)sW[ff];
        #pragma unroll
        for (int rp = 0; rp < 8; rp++) {
            unsigned long long tt = pw[rp];
            FMA2(acc[rp], b2, tt);
        }
    }
    #pragma unroll
    for (int rp = 0; rp < 8; rp++) {
        float a, b; upk2(acc[rp], a, b);
        atomicAdd(&g_WxT[i][2 * rp], a);
        atomicAdd(&g_WxT[i][2 * rp + 1], b);
    }
}

// ============ k_out v3: smem-staged GEMV. Block = 32 b; 8 i-parts/thread ======
__global__ void __launch_bounds__(256) k_out(const float* __restrict__ x,
                                             float* __restrict__ out, int write_raw) {
    __shared__ float sx[32][129];                 // 16.5 KB, pad->conflict-free
    __shared__ __align__(16) float swt[128][16];  // 8 KB
    __shared__ float sp[8][32][16];               // 16 KB partials
    int t = threadIdx.x;
    int bl = t & 31, part = t >> 5;
    int bbase = blockIdx.x * 32;

    unsigned long long acc[8];
    #pragma unroll
    for (int rp = 0; rp < 8; rp++) acc[rp] = 0ull;

    for (int c = 0; c < 8; c++) {
        int i0 = c * 128;
        // stage x tile (coalesced): 32 b x 128 i
        #pragma unroll
        for (int idx = t; idx < 32 * 128; idx += 256) {
            int b = idx >> 7, i = idx & 127;
            sx[b][i] = __ldg(x + (size_t)(bbase + b) * IN_ + i0 + i);
        }
        // stage WxT chunk (coalesced): 128 i x 16 r
        #pragma unroll
        for (int idx = t; idx < 128 * 16; idx += 256)
            ((float*)swt)[idx] = ((const float*)g_WxT)[i0 * 16 + idx];
        __syncthreads();

        #pragma unroll
        for (int ii = 0; ii < 16; ii++) {
            int i = part * 16 + ii;
            float xv = sx[bl][i];
            unsigned long long ux = pk2(xv, xv);
            const ulonglong2* w = (const ulonglong2*)swt[i];
            ulonglong2 wA = w[0], wB = w[1], wC = w[2], wD = w[3];
            FMA2(acc[0], ux, wA.x); FMA2(acc[1], ux, wA.y);
            FMA2(acc[2], ux, wB.x); FMA2(acc[3], ux, wB.y);
            FMA2(acc[4], ux, wC.x); FMA2(acc[5], ux, wC.y);
            FMA2(acc[6], ux, wD.x); FMA2(acc[7], ux, wD.y);
        }
        __syncthreads();
    }

    // write partials
    #pragma unroll
    for (int rp = 0; rp < 8; rp++) {
        float a, b; upk2(acc[rp], a, b);
        sp[part][bl][2 * rp] = a;
        sp[part][bl][2 * rp + 1] = b;
    }
    __syncthreads();

    // reduce 8 parts: 512 (b,r) pairs, 2 per thread
    #pragma unroll
    for (int u = 0; u < 2; u++) {
        int pair = t * 2 + u;
        int b = pair >> 4, r = pair & 15;
        float s = 0.f;
        #pragma unroll
        for (int p = 0; p < 8; p++) s += sp[p][b][r];
        float v = s + g_cst[r];
        out[r * B_ + bbase + b] = 1.f / (1.f + expf(-v));
        if (write_raw) out[R_ * B_ + r * B_ + bbase + b] = v;
    }
}

// ---------------- launcher ----------------
extern "C" void kernel_launch(void* const* d_in, const int* in_sizes, int n_in,
                              void* d_out, int out_size) {
    const float* x      = (const float*)d_in[0];
    const float* pref   = (const float*)d_in[1];
    const float* base_w = (const float*)d_in[2];
    const float* base_b = (const float*)d_in[3];
    const float* wm1_w  = (const float*)d_in[4];
    const float* wm1_b  = (const float*)d_in[5];
    const float* wm2_w  = (const float*)d_in[6];
    const float* wm2_b  = (const float*)d_in[7];
    const float* ray0_w = (const float*)d_in[8];
    const float* ray0_b = (const float*)d_in[9];
    const float* ray2_w = (const float*)d_in[10];
    const float* ray2_b = (const float*)d_in[11];
    const float* fc1_w  = (const float*)d_in[12];
    const float* fc1_b  = (const float*)d_in[13];
    const float* b1_w   = (const float*)d_in[14];
    const float* b1_b   = (const float*)d_in[15];
    const float* fc2_w  = (const float*)d_in[16];
    const float* fc2_b  = (const float*)d_in[17];
    const float* b2_w   = (const float*)d_in[18];
    const float* b2_b   = (const float*)d_in[19];
    float* out = (float*)d_out;
    int write_raw = (out_size >= 2 * R_ * B_) ? 1 : 0;

    k_head<<<R_, 256>>>(pref, wm1_w, wm1_b, wm2_w, wm2_b,
                        ray0_w, ray0_b, ray2_w, ray2_b,
                        fc2_w, fc2_b, b1_w, b1_b, b2_w, b2_b);
    k_weff<<<dim3(F_ / 8, NSEG_), 256>>>(fc1_w, fc1_b);
    k_wx<<<dim3(8, 16), 128>>>(base_w, base_b);
    k_out<<<B_ / 32, 256>>>(x, out, write_raw);   // launch #4 -> profiled
}